// round 2
// baseline (speedup 1.0000x reference)
#include <cuda_runtime.h>
#include <cuda_bf16.h>
#include <cstdint>

// GaussianKernel: N=32, R=128, F=128
// D[n,i,j] = sum_f (x1[n,i,f] - x2[n,j,f] - mean)^2
// k = exp(-D / (2 sigma^2)); out = softmax_j(k)

#define N_B 32
#define R_DIM 128
#define F_DIM 128
#define TI 16                 // i-rows per block
#define X2_STRIDE 132         // padded row stride (floats) for conflict-free LDS.128

// ---- f32x2 packed helpers (sm_103a) ----
__device__ __forceinline__ unsigned long long f32x2_add(unsigned long long a, unsigned long long b) {
    unsigned long long r;
    asm("add.rn.f32x2 %0, %1, %2;" : "=l"(r) : "l"(a), "l"(b));
    return r;
}
__device__ __forceinline__ unsigned long long f32x2_fma(unsigned long long a, unsigned long long b, unsigned long long c) {
    unsigned long long r;
    asm("fma.rn.f32x2 %0, %1, %2, %3;" : "=l"(r) : "l"(a), "l"(b), "l"(c));
    return r;
}
__device__ __forceinline__ void f32x2_unpack(unsigned long long u, float& lo, float& hi) {
    asm("mov.b64 {%0, %1}, %2;" : "=f"(lo), "=f"(hi) : "l"(u));
}

__global__ void __launch_bounds__(128, 2)
gaussian_kernel_softmax(const float4* __restrict__ x1,
                        const float4* __restrict__ x2,
                        const float* __restrict__ sigma,
                        const float* __restrict__ mean,
                        float* __restrict__ out) {
    extern __shared__ float smem[];
    float* x2s = smem;                               // [128][132] floats, holds -x2
    float* x1s = smem + R_DIM * X2_STRIDE;           // [TI][128] floats, holds x1 - mean
    float* red = x1s + TI * F_DIM;                   // [TI][4] warp partials

    const int n  = blockIdx.y;
    const int i0 = blockIdx.x * TI;
    const int t  = threadIdx.x;                      // t == j (0..127)
    const int lane = t & 31;
    const int warp = t >> 5;

    const float mn = mean[0];
    const float sg = sigma[0];
    const float inv2s2 = 1.0f / (2.0f * sg * sg);

    // ---- load -x2[n] into padded shared (coalesced float4 gmem reads) ----
    const float4* x2g = x2 + (size_t)n * (R_DIM * F_DIM / 4);
    #pragma unroll
    for (int it = 0; it < (R_DIM * F_DIM / 4) / 128; ++it) {
        int idx4 = t + 128 * it;            // 0..4095
        int row  = idx4 >> 5;               // 32 float4 per row
        int c4   = idx4 & 31;
        float4 v = x2g[idx4];
        float4 w = make_float4(-v.x, -v.y, -v.z, -v.w);
        *(float4*)&x2s[row * X2_STRIDE + c4 * 4] = w;
    }

    // ---- load x1 tile (TI rows), subtract mean ----
    const float4* x1g = x1 + (size_t)n * (R_DIM * F_DIM / 4) + (size_t)i0 * (F_DIM / 4);
    #pragma unroll
    for (int it = 0; it < (TI * F_DIM / 4) / 128; ++it) {
        int idx4 = t + 128 * it;            // 0..511
        float4 v = x1g[idx4];
        float4 w = make_float4(v.x - mn, v.y - mn, v.z - mn, v.w - mn);
        *(float4*)&x1s[idx4 * 4] = w;
    }
    __syncthreads();

    // ---- main loop: thread t owns column j=t; TI accumulators in f32x2 ----
    unsigned long long acc[TI];
    #pragma unroll
    for (int ii = 0; ii < TI; ++ii) acc[ii] = 0ull;   // (0.0f, 0.0f)

    const ulonglong2* brow = (const ulonglong2*)&x2s[t * X2_STRIDE];

    #pragma unroll 2
    for (int f4 = 0; f4 < F_DIM / 4; ++f4) {
        ulonglong2 b = brow[f4];                       // -x2[j, 4f..4f+3]
        #pragma unroll
        for (int ii = 0; ii < TI; ++ii) {
            ulonglong2 a = *(const ulonglong2*)&x1s[ii * F_DIM + f4 * 4];
            unsigned long long d0 = f32x2_add(a.x, b.x);
            acc[ii] = f32x2_fma(d0, d0, acc[ii]);
            unsigned long long d1 = f32x2_add(a.y, b.y);
            acc[ii] = f32x2_fma(d1, d1, acc[ii]);
        }
    }

    // ---- kernel value + softmax numerator ----
    float ex[TI];
    #pragma unroll
    for (int ii = 0; ii < TI; ++ii) {
        float lo, hi;
        f32x2_unpack(acc[ii], lo, hi);
        float d = lo + hi;
        float k = __expf(-d * inv2s2);     // in (0,1]
        ex[ii] = __expf(k);                // no max-sub needed: arg bounded
    }

    // ---- reduce sum over j (128 threads = 4 warps) ----
    #pragma unroll
    for (int ii = 0; ii < TI; ++ii) {
        float s = ex[ii];
        #pragma unroll
        for (int o = 16; o > 0; o >>= 1)
            s += __shfl_xor_sync(0xffffffffu, s, o);
        if (lane == 0) red[ii * 4 + warp] = s;
    }
    __syncthreads();

    // ---- normalize and write (coalesced over j) ----
    float* outp = out + ((size_t)n * R_DIM + i0) * R_DIM + t;
    #pragma unroll
    for (int ii = 0; ii < TI; ++ii) {
        float tot = red[ii * 4 + 0] + red[ii * 4 + 1] + red[ii * 4 + 2] + red[ii * 4 + 3];
        outp[ii * R_DIM] = ex[ii] / tot;
    }
}

extern "C" void kernel_launch(void* const* d_in, const int* in_sizes, int n_in,
                              void* d_out, int out_size) {
    const float4* x1    = (const float4*)d_in[0];
    const float4* x2    = (const float4*)d_in[1];
    const float*  sigma = (const float*)d_in[2];
    const float*  mean  = (const float*)d_in[3];
    float* out = (float*)d_out;

    const int smem_bytes = (R_DIM * X2_STRIDE + TI * F_DIM + TI * 4) * (int)sizeof(float);
    cudaFuncSetAttribute(gaussian_kernel_softmax,
                         cudaFuncAttributeMaxDynamicSharedMemorySize, smem_bytes);

    dim3 grid(R_DIM / TI, N_B);   // (8, 32) = 256 blocks
    dim3 block(128);
    gaussian_kernel_softmax<<<grid, block, smem_bytes>>>(x1, x2, sigma, mean, out);
}

// round 3
// speedup vs baseline: 1.0489x; 1.0489x over previous
#include <cuda_runtime.h>
#include <cuda_bf16.h>
#include <cstdint>

// GaussianKernel: N=32, R=128, F=128
// D[n,i,j] = sum_f (x1[n,i,f] - x2[n,j,f] - mean)^2
// k = exp(-D / (2 sigma^2)); out = softmax_j(k)

#define N_B 32
#define R_DIM 128
#define F_DIM 128
#define TI 16                 // i-rows per block
#define X2_STRIDE 132         // padded row stride (floats) for conflict-free LDS.128

// ---- f32x2 packed helpers (sm_103a) ----
__device__ __forceinline__ unsigned long long f32x2_add(unsigned long long a, unsigned long long b) {
    unsigned long long r;
    asm("add.rn.f32x2 %0, %1, %2;" : "=l"(r) : "l"(a), "l"(b));
    return r;
}
__device__ __forceinline__ unsigned long long f32x2_fma(unsigned long long a, unsigned long long b, unsigned long long c) {
    unsigned long long r;
    asm("fma.rn.f32x2 %0, %1, %2, %3;" : "=l"(r) : "l"(a), "l"(b), "l"(c));
    return r;
}
__device__ __forceinline__ void f32x2_unpack(unsigned long long u, float& lo, float& hi) {
    asm("mov.b64 {%0, %1}, %2;" : "=f"(lo), "=f"(hi) : "l"(u));
}

__global__ void __launch_bounds__(128, 2)
gaussian_kernel_softmax(const float4* __restrict__ x1,
                        const float4* __restrict__ x2,
                        const float* __restrict__ sigma,
                        const float* __restrict__ mean,
                        float* __restrict__ out) {
    extern __shared__ float smem[];
    float* x2s = smem;                               // [128][132] floats, holds -x2
    float* x1s = smem + R_DIM * X2_STRIDE;           // [TI][128] floats, holds x1 - mean
    float* red = x1s + TI * F_DIM;                   // [TI][4] warp partials

    const int n  = blockIdx.y;
    const int i0 = blockIdx.x * TI;
    const int t  = threadIdx.x;                      // t == j (0..127)
    const int lane = t & 31;
    const int warp = t >> 5;

    const float mn = mean[0];
    const float sg = sigma[0];
    const float inv2s2 = 1.0f / (2.0f * sg * sg);

    // ---- load -x2[n] into padded shared (coalesced float4 gmem reads) ----
    const float4* x2g = x2 + (size_t)n * (R_DIM * F_DIM / 4);
    #pragma unroll
    for (int it = 0; it < (R_DIM * F_DIM / 4) / 128; ++it) {
        int idx4 = t + 128 * it;            // 0..4095
        int row  = idx4 >> 5;               // 32 float4 per row
        int c4   = idx4 & 31;
        float4 v = x2g[idx4];
        float4 w = make_float4(-v.x, -v.y, -v.z, -v.w);
        *(float4*)&x2s[row * X2_STRIDE + c4 * 4] = w;
    }

    // ---- load x1 tile (TI rows), subtract mean ----
    const float4* x1g = x1 + (size_t)n * (R_DIM * F_DIM / 4) + (size_t)i0 * (F_DIM / 4);
    #pragma unroll
    for (int it = 0; it < (TI * F_DIM / 4) / 128; ++it) {
        int idx4 = t + 128 * it;            // 0..511
        float4 v = x1g[idx4];
        float4 w = make_float4(v.x - mn, v.y - mn, v.z - mn, v.w - mn);
        *(float4*)&x1s[idx4 * 4] = w;
    }
    __syncthreads();

    // ---- main loop: thread t owns column j=t; TI accumulators in f32x2 ----
    unsigned long long acc[TI];
    #pragma unroll
    for (int ii = 0; ii < TI; ++ii) acc[ii] = 0ull;   // (0.0f, 0.0f)

    const ulonglong2* brow = (const ulonglong2*)&x2s[t * X2_STRIDE];

    #pragma unroll 2
    for (int f4 = 0; f4 < F_DIM / 4; ++f4) {
        ulonglong2 b = brow[f4];                       // -x2[j, 4f..4f+3]
        #pragma unroll
        for (int ii = 0; ii < TI; ++ii) {
            ulonglong2 a = *(const ulonglong2*)&x1s[ii * F_DIM + f4 * 4];
            unsigned long long d0 = f32x2_add(a.x, b.x);
            acc[ii] = f32x2_fma(d0, d0, acc[ii]);
            unsigned long long d1 = f32x2_add(a.y, b.y);
            acc[ii] = f32x2_fma(d1, d1, acc[ii]);
        }
    }

    // ---- kernel value + softmax numerator ----
    float ex[TI];
    #pragma unroll
    for (int ii = 0; ii < TI; ++ii) {
        float lo, hi;
        f32x2_unpack(acc[ii], lo, hi);
        float d = lo + hi;
        float k = __expf(-d * inv2s2);     // in (0,1]
        ex[ii] = __expf(k);                // no max-sub needed: arg bounded
    }

    // ---- reduce sum over j (128 threads = 4 warps) ----
    #pragma unroll
    for (int ii = 0; ii < TI; ++ii) {
        float s = ex[ii];
        #pragma unroll
        for (int o = 16; o > 0; o >>= 1)
            s += __shfl_xor_sync(0xffffffffu, s, o);
        if (lane == 0) red[ii * 4 + warp] = s;
    }
    __syncthreads();

    // ---- normalize and write (coalesced over j) ----
    float* outp = out + ((size_t)n * R_DIM + i0) * R_DIM + t;
    #pragma unroll
    for (int ii = 0; ii < TI; ++ii) {
        float tot = red[ii * 4 + 0] + red[ii * 4 + 1] + red[ii * 4 + 2] + red[ii * 4 + 3];
        outp[ii * R_DIM] = ex[ii] / tot;
    }
}

extern "C" void kernel_launch(void* const* d_in, const int* in_sizes, int n_in,
                              void* d_out, int out_size) {
    const float4* x1    = (const float4*)d_in[0];
    const float4* x2    = (const float4*)d_in[1];
    const float*  sigma = (const float*)d_in[2];
    const float*  mean  = (const float*)d_in[3];
    float* out = (float*)d_out;

    const int smem_bytes = (R_DIM * X2_STRIDE + TI * F_DIM + TI * 4) * (int)sizeof(float);
    cudaFuncSetAttribute(gaussian_kernel_softmax,
                         cudaFuncAttributeMaxDynamicSharedMemorySize, smem_bytes);

    dim3 grid(R_DIM / TI, N_B);   // (8, 32) = 256 blocks
    dim3 block(128);
    gaussian_kernel_softmax<<<grid, block, smem_bytes>>>(x1, x2, sigma, mean, out);
}

// round 4
// speedup vs baseline: 1.1830x; 1.1278x over previous
#include <cuda_runtime.h>
#include <cuda_bf16.h>
#include <cstdint>

// GaussianKernel: N=32, R=128, F=128
// Gram form: D[i,j] = ||u_i||^2 - 2 u_i.v_j + ||v_j||^2,  u = x1 - mean, v = x2
// k = exp(-D / (2 sigma^2)); out = softmax_j(exp(k))

#define N_B 32
#define R_DIM 128
#define F_DIM 128
#define TIB 16          // i-rows per block
#define TIT 8           // i-rows per thread (one of two groups)
#define X2_STRIDE 132   // padded row stride (floats): conflict-free LDS.128

__device__ __forceinline__ unsigned long long f32x2_fma(unsigned long long a, unsigned long long b, unsigned long long c) {
    unsigned long long r;
    asm("fma.rn.f32x2 %0, %1, %2, %3;" : "=l"(r) : "l"(a), "l"(b), "l"(c));
    return r;
}
__device__ __forceinline__ void f32x2_unpack(unsigned long long u, float& lo, float& hi) {
    asm("mov.b64 {%0, %1}, %2;" : "=f"(lo), "=f"(hi) : "l"(u));
}

__global__ void __launch_bounds__(256, 3)
gaussian_gram_softmax(const float4* __restrict__ x1,
                      const float4* __restrict__ x2,
                      const float* __restrict__ sigma,
                      const float* __restrict__ mean,
                      float* __restrict__ out) {
    extern __shared__ float smem[];
    float* x2s   = smem;                         // [128][132]  v
    float* x1s   = x2s + R_DIM * X2_STRIDE;      // [16][128]   u = x1 - mean
    float* normu = x1s + TIB * F_DIM;            // [16]
    float* red   = normu + TIB;                  // [16][4] warp partials

    const int n    = blockIdx.y;
    const int i0   = blockIdx.x * TIB;
    const int t    = threadIdx.x;
    const int j    = t & 127;                    // column owned by this thread
    const int g    = t >> 7;                     // i-row group (0/1)
    const int lane = t & 31;
    const int gw   = (t >> 5) & 3;               // warp within group

    const float mn = mean[0];
    const float sg = sigma[0];
    const float inv2s2 = 1.0f / (2.0f * sg * sg);

    // ---- load v = x2[n] into padded shared (coalesced float4) ----
    const float4* x2g = x2 + (size_t)n * (R_DIM * F_DIM / 4);
    #pragma unroll
    for (int it = 0; it < (R_DIM * F_DIM / 4) / 256; ++it) {
        int idx4 = t + 256 * it;                 // 0..4095
        int row  = idx4 >> 5;
        int c4   = idx4 & 31;
        *(float4*)&x2s[row * X2_STRIDE + c4 * 4] = x2g[idx4];
    }

    // ---- load u = x1 tile - mean ----
    const float4* x1g = x1 + ((size_t)n * R_DIM + i0) * (F_DIM / 4);
    #pragma unroll
    for (int it = 0; it < (TIB * F_DIM / 4) / 256; ++it) {
        int idx4 = t + 256 * it;                 // 0..511
        float4 v = x1g[idx4];
        *(float4*)&x1s[idx4 * 4] = make_float4(v.x - mn, v.y - mn, v.z - mn, v.w - mn);
    }
    __syncthreads();

    // ---- normu: thread t<128 -> row r = t>>3, 16-float chunk c = t&7 ----
    if (t < 128) {
        int r = t >> 3, c = t & 7;
        const ulonglong2* up = (const ulonglong2*)&x1s[r * F_DIM + c * 16];
        unsigned long long accu = 0ull;
        #pragma unroll
        for (int q = 0; q < 4; ++q) {
            ulonglong2 a = up[q];
            accu = f32x2_fma(a.x, a.x, accu);
            accu = f32x2_fma(a.y, a.y, accu);
        }
        float lo, hi; f32x2_unpack(accu, lo, hi);
        float s = lo + hi;
        s += __shfl_xor_sync(0xffffffffu, s, 1);
        s += __shfl_xor_sync(0xffffffffu, s, 2);
        s += __shfl_xor_sync(0xffffffffu, s, 4);
        if ((t & 7) == 0) normu[r] = s;
    }

    // ---- main: dot(u_i, v_j) for TIT rows; fold ||v_j||^2 in (reuses b) ----
    unsigned long long acc[TIT];
    #pragma unroll
    for (int ii = 0; ii < TIT; ++ii) acc[ii] = 0ull;
    unsigned long long accv = 0ull;

    const ulonglong2* brow = (const ulonglong2*)&x2s[j * X2_STRIDE];
    const float* arow = &x1s[g * TIT * F_DIM];

    #pragma unroll 8
    for (int f4 = 0; f4 < F_DIM / 4; ++f4) {
        ulonglong2 b = brow[f4];
        accv = f32x2_fma(b.x, b.x, accv);
        accv = f32x2_fma(b.y, b.y, accv);
        #pragma unroll
        for (int ii = 0; ii < TIT; ++ii) {
            ulonglong2 a = *(const ulonglong2*)&arow[ii * F_DIM + f4 * 4];
            acc[ii] = f32x2_fma(a.x, b.x, acc[ii]);
            acc[ii] = f32x2_fma(a.y, b.y, acc[ii]);
        }
    }

    float lo, hi;
    f32x2_unpack(accv, lo, hi);
    const float nv = lo + hi;

    __syncthreads();   // normu writes visible

    // ---- kernel value + softmax numerator ----
    float ex[TIT];
    #pragma unroll
    for (int ii = 0; ii < TIT; ++ii) {
        f32x2_unpack(acc[ii], lo, hi);
        float dot = lo + hi;
        float D = normu[g * TIT + ii] + nv - 2.0f * dot;
        float k = __expf(-D * inv2s2);           // in (0,1]
        ex[ii] = __expf(k);                      // bounded arg, no max-sub
    }

    // ---- reduce over j within each 128-thread group (4 warps) ----
    #pragma unroll
    for (int ii = 0; ii < TIT; ++ii) {
        float s = ex[ii];
        #pragma unroll
        for (int o = 16; o > 0; o >>= 1)
            s += __shfl_xor_sync(0xffffffffu, s, o);
        if (lane == 0) red[(g * TIT + ii) * 4 + gw] = s;
    }
    __syncthreads();

    // ---- normalize and write (coalesced over j) ----
    float* outp = out + ((size_t)n * R_DIM + i0 + g * TIT) * R_DIM + j;
    #pragma unroll
    for (int ii = 0; ii < TIT; ++ii) {
        const float* rp = &red[(g * TIT + ii) * 4];
        float tot = rp[0] + rp[1] + rp[2] + rp[3];
        outp[ii * R_DIM] = ex[ii] * (1.0f / tot);
    }
}

extern "C" void kernel_launch(void* const* d_in, const int* in_sizes, int n_in,
                              void* d_out, int out_size) {
    const float4* x1    = (const float4*)d_in[0];
    const float4* x2    = (const float4*)d_in[1];
    const float*  sigma = (const float*)d_in[2];
    const float*  mean  = (const float*)d_in[3];
    float* out = (float*)d_out;

    const int smem_bytes = (R_DIM * X2_STRIDE + TIB * F_DIM + TIB + TIB * 4) * (int)sizeof(float);
    cudaFuncSetAttribute(gaussian_gram_softmax,
                         cudaFuncAttributeMaxDynamicSharedMemorySize, smem_bytes);

    dim3 grid(R_DIM / TIB, N_B);   // (8, 32) = 256 blocks, single wave at 3/SM
    dim3 block(256);
    gaussian_gram_softmax<<<grid, block, smem_bytes>>>(x1, x2, sigma, mean, out);
}

// round 5
// speedup vs baseline: 1.4090x; 1.1910x over previous
#include <cuda_runtime.h>
#include <cuda_bf16.h>
#include <cstdint>

// GaussianKernel: N=32, R=128, F=128
// Gram form: D[i,j] = ||u_i||^2 - 2 u_i.v_j + ||v_j||^2,  u = x1 - mean, v = x2
// out = softmax_j( exp( exp(-D/(2 sigma^2)) ) )  [softmax of kernel value]
//
// Layout: 128 blocks (one per SM), 256 threads.
// Block: 32 i-rows x 128 j. Thread: 4i x 4j register tile.
// warp w owns i-rows {4w..4w+3}; lane owns j in {lane, lane+32, lane+64, lane+96}
// -> softmax reduction is warp-local (pure shfl).

#define N_B 32
#define R_DIM 128
#define F_DIM 128
#define TIB 32          // i-rows per block
#define X2_STRIDE 132   // padded row stride (floats): conflict-free LDS.128

__device__ __forceinline__ unsigned long long f32x2_fma(unsigned long long a, unsigned long long b, unsigned long long c) {
    unsigned long long r;
    asm("fma.rn.f32x2 %0, %1, %2, %3;" : "=l"(r) : "l"(a), "l"(b), "l"(c));
    return r;
}
__device__ __forceinline__ void f32x2_unpack(unsigned long long u, float& lo, float& hi) {
    asm("mov.b64 {%0, %1}, %2;" : "=f"(lo), "=f"(hi) : "l"(u));
}

__global__ void __launch_bounds__(256, 2)
gaussian_gram_rt(const float4* __restrict__ x1,
                 const float4* __restrict__ x2,
                 const float* __restrict__ sigma,
                 const float* __restrict__ mean,
                 float* __restrict__ out) {
    extern __shared__ float smem[];
    float* x2s   = smem;                         // [128][132]  v
    float* x1s   = x2s + R_DIM * X2_STRIDE;      // [32][128]   u = x1 - mean
    float* normu = x1s + TIB * F_DIM;            // [32]

    const int n    = blockIdx.y;
    const int i0   = blockIdx.x * TIB;
    const int t    = threadIdx.x;
    const int lane = t & 31;
    const int warp = t >> 5;                     // 0..7 -> i-rows 4w..4w+3

    const float mn = mean[0];
    const float sg = sigma[0];
    const float inv2s2 = 1.0f / (2.0f * sg * sg);

    // ---- fill v = x2[n] into padded smem (coalesced float4) ----
    const float4* x2g = x2 + (size_t)n * (R_DIM * F_DIM / 4);
    #pragma unroll
    for (int it = 0; it < (R_DIM * F_DIM / 4) / 256; ++it) {
        int idx4 = t + 256 * it;                 // 0..4095
        int row  = idx4 >> 5;
        int c4   = idx4 & 31;
        *(float4*)&x2s[row * X2_STRIDE + c4 * 4] = x2g[idx4];
    }

    // ---- fill u = x1 tile - mean ----
    const float4* x1g = x1 + ((size_t)n * R_DIM + i0) * (F_DIM / 4);
    #pragma unroll
    for (int it = 0; it < (TIB * F_DIM / 4) / 256; ++it) {
        int idx4 = t + 256 * it;                 // 0..1023
        float4 v = x1g[idx4];
        *(float4*)&x1s[idx4 * 4] = make_float4(v.x - mn, v.y - mn, v.z - mn, v.w - mn);
    }
    __syncthreads();

    // ---- normu: thread t -> row r = t>>3, 16-float chunk c = t&7 ----
    {
        int r = t >> 3, c = t & 7;               // 32 rows x 8 chunks = 256 threads
        const ulonglong2* up = (const ulonglong2*)&x1s[r * F_DIM + c * 16];
        unsigned long long accu = 0ull;
        #pragma unroll
        for (int q = 0; q < 4; ++q) {
            ulonglong2 a = up[q];
            accu = f32x2_fma(a.x, a.x, accu);
            accu = f32x2_fma(a.y, a.y, accu);
        }
        float lo, hi; f32x2_unpack(accu, lo, hi);
        float s = lo + hi;
        s += __shfl_xor_sync(0xffffffffu, s, 1);
        s += __shfl_xor_sync(0xffffffffu, s, 2);
        s += __shfl_xor_sync(0xffffffffu, s, 4);
        if ((t & 7) == 0) normu[r] = s;
    }
    __syncthreads();

    // ---- main loop: 4i x 4j register tile, fold ||v_j||^2 in ----
    unsigned long long acc[4][4];                // [i][j] f32x2 dot partials
    #pragma unroll
    for (int r = 0; r < 4; ++r)
        #pragma unroll
        for (int q = 0; q < 4; ++q) acc[r][q] = 0ull;
    unsigned long long accv[4] = {0ull, 0ull, 0ull, 0ull};

    const ulonglong2* brow = (const ulonglong2*)&x2s[lane * X2_STRIDE]; // + q*32 rows
    const float* arow = &x1s[warp * 4 * F_DIM];
    const int bq_stride = 32 * X2_STRIDE / 4;    // ulonglong2 units per 32 rows

    #pragma unroll 4
    for (int f4 = 0; f4 < F_DIM / 4; ++f4) {
        ulonglong2 b[4];
        #pragma unroll
        for (int q = 0; q < 4; ++q) b[q] = brow[q * bq_stride + f4];
        ulonglong2 a[4];
        #pragma unroll
        for (int r = 0; r < 4; ++r) a[r] = *(const ulonglong2*)&arow[r * F_DIM + f4 * 4];

        #pragma unroll
        for (int q = 0; q < 4; ++q) {
            accv[q] = f32x2_fma(b[q].x, b[q].x, accv[q]);
            accv[q] = f32x2_fma(b[q].y, b[q].y, accv[q]);
        }
        #pragma unroll
        for (int r = 0; r < 4; ++r)
            #pragma unroll
            for (int q = 0; q < 4; ++q) {
                acc[r][q] = f32x2_fma(a[r].x, b[q].x, acc[r][q]);
                acc[r][q] = f32x2_fma(a[r].y, b[q].y, acc[r][q]);
            }
    }

    // ---- epilogue: kernel value, double-exp, warp-local softmax ----
    float nv[4];
    #pragma unroll
    for (int q = 0; q < 4; ++q) {
        float lo, hi; f32x2_unpack(accv[q], lo, hi);
        nv[q] = lo + hi;
    }

    float* outbase = out + ((size_t)n * R_DIM + i0 + warp * 4) * R_DIM;

    #pragma unroll
    for (int r = 0; r < 4; ++r) {
        const float nu = normu[warp * 4 + r];
        float ex[4];
        float s = 0.0f;
        #pragma unroll
        for (int q = 0; q < 4; ++q) {
            float lo, hi; f32x2_unpack(acc[r][q], lo, hi);
            float D = nu + nv[q] - 2.0f * (lo + hi);
            float k = __expf(-D * inv2s2);       // in (0,1]
            ex[q] = __expf(k);                   // bounded arg, no max-sub
            s += ex[q];
        }
        #pragma unroll
        for (int o = 16; o > 0; o >>= 1)
            s += __shfl_xor_sync(0xffffffffu, s, o);
        const float inv = 1.0f / s;
        #pragma unroll
        for (int q = 0; q < 4; ++q)
            outbase[r * R_DIM + lane + 32 * q] = ex[q] * inv;
    }
}

extern "C" void kernel_launch(void* const* d_in, const int* in_sizes, int n_in,
                              void* d_out, int out_size) {
    const float4* x1    = (const float4*)d_in[0];
    const float4* x2    = (const float4*)d_in[1];
    const float*  sigma = (const float*)d_in[2];
    const float*  mean  = (const float*)d_in[3];
    float* out = (float*)d_out;

    const int smem_bytes = (R_DIM * X2_STRIDE + TIB * F_DIM + TIB) * (int)sizeof(float);
    cudaFuncSetAttribute(gaussian_gram_rt,
                         cudaFuncAttributeMaxDynamicSharedMemorySize, smem_bytes);

    dim3 grid(R_DIM / TIB, N_B);   // (4, 32) = 128 blocks -> exactly 1 per SM
    dim3 block(256);
    gaussian_gram_rt<<<grid, block, smem_bytes>>>(x1, x2, sigma, mean, out);
}